// round 7
// baseline (speedup 1.0000x reference)
#include <cuda_runtime.h>

#define BN 4096
#define DN 768
#define PN 96
#define CN 256
#define SDN 8

typedef unsigned long long u64;

__device__ __forceinline__ u64 ffma2(u64 a, u64 b, u64 c) {
    u64 d;
    asm("fma.rn.f32x2 %0, %1, %2, %3;" : "=l"(d) : "l"(a), "l"(b), "l"(c));
    return d;
}
__device__ __forceinline__ u64 fadd2(u64 a, u64 b) {
    u64 d;
    asm("add.rn.f32x2 %0, %1, %2;" : "=l"(d) : "l"(a), "l"(b));
    return d;
}
__device__ __forceinline__ u64 pack2(float lo, float hi) {
    u64 r;
    asm("mov.b64 %0, {%1, %2};" : "=l"(r) : "f"(lo), "f"(hi));
    return r;
}
__device__ __forceinline__ void unpack2(u64 v, float& lo, float& hi) {
    asm("mov.b64 {%0, %1}, %2;" : "=f"(lo), "=f"(hi) : "l"(v));
}

// v_sq / c_sq with the reference's rounding: elementwise square (rn), then
// strictly sequential adds (rn), no fma contraction.
__device__ __forceinline__ float sumsq8(float4 lo, float4 hi) {
    float q = __fmul_rn(lo.x, lo.x);
    q = __fadd_rn(q, __fmul_rn(lo.y, lo.y));
    q = __fadd_rn(q, __fmul_rn(lo.z, lo.z));
    q = __fadd_rn(q, __fmul_rn(lo.w, lo.w));
    q = __fadd_rn(q, __fmul_rn(hi.x, hi.x));
    q = __fadd_rn(q, __fmul_rn(hi.y, hi.y));
    q = __fadd_rn(q, __fmul_rn(hi.z, hi.z));
    q = __fadd_rn(q, __fmul_rn(hi.w, hi.w));
    return q;
}

// Block: 128 threads, covers 512 batch vectors (4 per thread) for one partition.
// Grid: (BN/512 = 8, PN = 96).
__global__ __launch_bounds__(128) void pq_argmax_kernel(
    const float* __restrict__ vecs,
    const float* __restrict__ codebook,
    float* __restrict__ out)
{
    // Pair-interleaved codebook: row j (16 floats) = {c0_d0,c1_d0,c0_d1,c1_d1,...}
    // where c0 = 2j, c1 = 2j+1. One LDS.128 yields two packed f32x2 operands.
    __shared__ __align__(16) float cbi[CN * SDN];
    __shared__ __align__(8)  float csq[CN];   // +||c||^2, natural c order

    const int t = threadIdx.x;
    const int p = blockIdx.y;
    const float* cb = codebook + (size_t)p * CN * SDN;

    // ---- init: thread t stages centroid pair (2t, 2t+1) ----
    {
        const float4* cb4 = (const float4*)cb + t * 4;
        float4 c0lo = cb4[0], c0hi = cb4[1];   // centroid 2t,   dims 0-3 / 4-7
        float4 c1lo = cb4[2], c1hi = cb4[3];   // centroid 2t+1

        float4* row = (float4*)(cbi + t * 16);
        row[0] = make_float4(c0lo.x, c1lo.x, c0lo.y, c1lo.y);
        row[1] = make_float4(c0lo.z, c1lo.z, c0lo.w, c1lo.w);
        row[2] = make_float4(c0hi.x, c1hi.x, c0hi.y, c1hi.y);
        row[3] = make_float4(c0hi.z, c1hi.z, c0hi.w, c1hi.w);
        csq[2 * t]     = sumsq8(c0lo, c0hi);
        csq[2 * t + 1] = sumsq8(c1lo, c1hi);
    }

    // ---- load the four sub-vectors this thread owns ----
    const int b0 = blockIdx.x * 512 + t;          // +0, +128, +256, +384
    const float4* v0 = (const float4*)(vecs + (size_t)b0 * DN + p * SDN);
    const float4* v1 = (const float4*)(vecs + (size_t)(b0 + 128) * DN + p * SDN);
    const float4* v2 = (const float4*)(vecs + (size_t)(b0 + 256) * DN + p * SDN);
    const float4* v3 = (const float4*)(vecs + (size_t)(b0 + 384) * DN + p * SDN);
    float4 a0 = v0[0], a1 = v0[1];
    float4 b0v = v1[0], b1v = v1[1];
    float4 c0v = v2[0], c1v = v2[1];
    float4 d0v = v3[0], d1v = v3[1];

    u64 wa[8], wb[8], wc[8], wd[8];
    wa[0] = pack2(a0.x, a0.x); wa[1] = pack2(a0.y, a0.y);
    wa[2] = pack2(a0.z, a0.z); wa[3] = pack2(a0.w, a0.w);
    wa[4] = pack2(a1.x, a1.x); wa[5] = pack2(a1.y, a1.y);
    wa[6] = pack2(a1.z, a1.z); wa[7] = pack2(a1.w, a1.w);
    wb[0] = pack2(b0v.x, b0v.x); wb[1] = pack2(b0v.y, b0v.y);
    wb[2] = pack2(b0v.z, b0v.z); wb[3] = pack2(b0v.w, b0v.w);
    wb[4] = pack2(b1v.x, b1v.x); wb[5] = pack2(b1v.y, b1v.y);
    wb[6] = pack2(b1v.z, b1v.z); wb[7] = pack2(b1v.w, b1v.w);
    wc[0] = pack2(c0v.x, c0v.x); wc[1] = pack2(c0v.y, c0v.y);
    wc[2] = pack2(c0v.z, c0v.z); wc[3] = pack2(c0v.w, c0v.w);
    wc[4] = pack2(c1v.x, c1v.x); wc[5] = pack2(c1v.y, c1v.y);
    wc[6] = pack2(c1v.z, c1v.z); wc[7] = pack2(c1v.w, c1v.w);
    wd[0] = pack2(d0v.x, d0v.x); wd[1] = pack2(d0v.y, d0v.y);
    wd[2] = pack2(d0v.z, d0v.z); wd[3] = pack2(d0v.w, d0v.w);
    wd[4] = pack2(d1v.x, d1v.x); wd[5] = pack2(d1v.y, d1v.y);
    wd[6] = pack2(d1v.z, d1v.z); wd[7] = pack2(d1v.w, d1v.w);

    const u64 vsqA = pack2(sumsq8(a0, a1),  sumsq8(a0, a1));
    const u64 vsqB = pack2(sumsq8(b0v, b1v), sumsq8(b0v, b1v));
    const u64 vsqC = pack2(sumsq8(c0v, c1v), sumsq8(c0v, c1v));
    const u64 vsqD = pack2(sumsq8(d0v, d1v), sumsq8(d0v, d1v));

    __syncthreads();

    // 2*vc is exact in fp32 (exponent bump), so the reference's
    //   m = rn(2*vc); d = rn(v_sq - m)
    // equals the single fma  d = rn(v_sq - 2*vc) = fma(vc, -2, v_sq).
    const u64 NEG2 = pack2(-2.0f, -2.0f);
    const ulonglong2* rows = (const ulonglong2*)cbi;
    const u64* nq = (const u64*)csq;

    float bestA = 3.402823466e+38f, bestB = 3.402823466e+38f;
    float bestC = 3.402823466e+38f, bestD = 3.402823466e+38f;
    int bjA = 0, bjB = 0, bjC = 0, bjD = 0;   // winning PAIR index

    #pragma unroll 4
    for (int j = 0; j < CN / 2; ++j) {
        ulonglong2 r0 = rows[j * 4 + 0];   // d0, d1 (each u64 = {c_even, c_odd})
        ulonglong2 r1 = rows[j * 4 + 1];   // d2, d3
        ulonglong2 r2 = rows[j * 4 + 2];   // d4, d5
        ulonglong2 r3 = rows[j * 4 + 3];   // d6, d7
        u64 q = nq[j];                     // {csq_even, csq_odd}

        u64 accA = 0ULL, accB = 0ULL, accC = 0ULL, accD = 0ULL;
        accA = ffma2(wa[0], r0.x, accA); accB = ffma2(wb[0], r0.x, accB);
        accC = ffma2(wc[0], r0.x, accC); accD = ffma2(wd[0], r0.x, accD);
        accA = ffma2(wa[1], r0.y, accA); accB = ffma2(wb[1], r0.y, accB);
        accC = ffma2(wc[1], r0.y, accC); accD = ffma2(wd[1], r0.y, accD);
        accA = ffma2(wa[2], r1.x, accA); accB = ffma2(wb[2], r1.x, accB);
        accC = ffma2(wc[2], r1.x, accC); accD = ffma2(wd[2], r1.x, accD);
        accA = ffma2(wa[3], r1.y, accA); accB = ffma2(wb[3], r1.y, accB);
        accC = ffma2(wc[3], r1.y, accC); accD = ffma2(wd[3], r1.y, accD);
        accA = ffma2(wa[4], r2.x, accA); accB = ffma2(wb[4], r2.x, accB);
        accC = ffma2(wc[4], r2.x, accC); accD = ffma2(wd[4], r2.x, accD);
        accA = ffma2(wa[5], r2.y, accA); accB = ffma2(wb[5], r2.y, accB);
        accC = ffma2(wc[5], r2.y, accC); accD = ffma2(wd[5], r2.y, accD);
        accA = ffma2(wa[6], r3.x, accA); accB = ffma2(wb[6], r3.x, accB);
        accC = ffma2(wc[6], r3.x, accC); accD = ffma2(wd[6], r3.x, accD);
        accA = ffma2(wa[7], r3.y, accA); accB = ffma2(wb[7], r3.y, accB);
        accC = ffma2(wc[7], r3.y, accC); accD = ffma2(wd[7], r3.y, accD);

        u64 sA = fadd2(ffma2(accA, NEG2, vsqA), q);
        u64 sB = fadd2(ffma2(accB, NEG2, vsqB), q);
        u64 sC = fadd2(ffma2(accC, NEG2, vsqC), q);
        u64 sD = fadd2(ffma2(accD, NEG2, vsqD), q);

        float s0, s1;
        // Index-free tournament: strict '<' on the pair-min keeps the earliest
        // pair on exact ties (matches jnp.argmax first-index on proba = -s).
        unpack2(sA, s0, s1);
        { float lv = fminf(s0, s1); bool m = lv < bestA;
          bestA = fminf(bestA, lv); if (m) bjA = j; }
        unpack2(sB, s0, s1);
        { float lv = fminf(s0, s1); bool m = lv < bestB;
          bestB = fminf(bestB, lv); if (m) bjB = j; }
        unpack2(sC, s0, s1);
        { float lv = fminf(s0, s1); bool m = lv < bestC;
          bestC = fminf(bestC, lv); if (m) bjC = j; }
        unpack2(sD, s0, s1);
        { float lv = fminf(s0, s1); bool m = lv < bestD;
          bestD = fminf(bestD, lv); if (m) bjD = j; }
    }

    // ---- epilogue: recompute ONLY the winning pair per b to resolve the
    // even/odd lane. Identical op sequence => bitwise-identical scores.
    // Even lane wins ties (strict s1 < s0).
    const u64* wsel[4] = { wa, wb, wc, wd };
    const u64  vsel[4] = { vsqA, vsqB, vsqC, vsqD };
    const int  jsel[4] = { bjA, bjB, bjC, bjD };

    #pragma unroll
    for (int g = 0; g < 4; ++g) {
        const u64* w = wsel[g];
        int bj = jsel[g];
        ulonglong2 r0 = rows[bj * 4 + 0], r1 = rows[bj * 4 + 1];
        ulonglong2 r2 = rows[bj * 4 + 2], r3 = rows[bj * 4 + 3];
        u64 q = nq[bj];
        u64 acc = 0ULL;
        acc = ffma2(w[0], r0.x, acc); acc = ffma2(w[1], r0.y, acc);
        acc = ffma2(w[2], r1.x, acc); acc = ffma2(w[3], r1.y, acc);
        acc = ffma2(w[4], r2.x, acc); acc = ffma2(w[5], r2.y, acc);
        acc = ffma2(w[6], r3.x, acc); acc = ffma2(w[7], r3.y, acc);
        u64 s = fadd2(ffma2(acc, NEG2, vsel[g]), q);
        float s0, s1; unpack2(s, s0, s1);
        int lane = (s1 < s0) ? 1 : 0;
        int base = bj * 16 + lane;

        float4 o0 = make_float4(cbi[base],      cbi[base + 2],
                                cbi[base + 4],  cbi[base + 6]);
        float4 o1 = make_float4(cbi[base + 8],  cbi[base + 10],
                                cbi[base + 12], cbi[base + 14]);
        float4* o = (float4*)(out + (size_t)(b0 + g * 128) * DN + p * SDN);
        o[0] = o0; o[1] = o1;
    }
}

extern "C" void kernel_launch(void* const* d_in, const int* in_sizes, int n_in,
                              void* d_out, int out_size) {
    const float* vecs     = (const float*)d_in[0];
    const float* codebook = (const float*)d_in[1];
    // Defensive: inputs are (vecs: B*D = 3145728, codebook: P*C*SD = 196608)
    if (n_in >= 2 && in_sizes[0] == PN * CN * SDN && in_sizes[1] == BN * DN) {
        const float* tmp = vecs; vecs = codebook; codebook = tmp;
    }
    float* out = (float*)d_out;
    dim3 grid(BN / 512, PN);
    pq_argmax_kernel<<<grid, 128>>>(vecs, codebook, out);
}